// round 8
// baseline (speedup 1.0000x reference)
#include <cuda_runtime.h>
#include <math.h>

// Fixed problem: C=1, H=W=2048
#define HH 2048
#define WW 2048
#define NMS_T 0.05f
#define KTOP 50

// Geometry: warp covers 26 output columns (lanes 3..28), 32 read columns
// (halo 3+3: conv radius 2 + maxpool radius 1). Strips: 79 x 14 = 1106,
// one strip per warp, 139 blocks x 8 warps -> single wave on 148 SMs.
#define OUTC 26
#define SX 79
#define SY 14
#define STRIPH 147          // 14*147 = 2058 >= 2048 (tail guarded by masked loads)
#define NSTRIP (SX*SY)      // 1106
#define WPB 8
#define NBLK 139            // ceil(1106/8); warps with s >= NSTRIP are inert
#define SLOTS 64            // per-block output slice (superset of block top-50)
#define NG (NBLK*SLOTS)     // 8896

#define CAPB 4352           // per-block candidate buffer (expected ~1500 peaks)
#define NBINS 2048
#define BINBASE 31385       // float_bits(0.05f) >> 15
#define BND 192
#define RING 16             // prefetch depth (register ring, fully unrolled)
#define PITER 160           // 10*RING >= STRIPH+6 loop iterations

__device__ unsigned long long g_cand[NG];

// key = (float_bits(raw) << 32) | (~idx): descending key order == lax.top_k
// order (value desc, ties -> lower flat index). bin1 is monotone in key.
__device__ __forceinline__ int keybin(unsigned long long k) {
    int b = (int)(k >> 47) - BINBASE;
    return b < 0 ? 0 : (b > NBINS - 1 ? NBINS - 1 : b);
}
// level-2 sub-bin: next 11 float bits (16-ulp granularity) within a bin1.
__device__ __forceinline__ int keybin2(unsigned long long k) {
    return (int)((unsigned)(k >> 36) & 0x7FFu);
}

// Warp 0: scan histogram top-down; find bin B with cum(>B) < target <= cum(>=B).
// Also returns cA = cum(>B). B = -1 (cA = total) if total < target.
__device__ __forceinline__ void find_thresh(const int* hist, int lane, int target,
                                            int* s_B, int* s_cA) {
    int cum = 0, B = -1, cA = 0;
    for (int base = NBINS - 32; base >= 0; base -= 32) {
        int h = hist[base + 31 - lane];          // lane 0 = highest bin of chunk
        int pfx = h;
#pragma unroll
        for (int off = 1; off < 32; off <<= 1) {
            int o = __shfl_up_sync(0xffffffffu, pfx, off);
            if (lane >= off) pfx += o;
        }
        int tot = __shfl_sync(0xffffffffu, pfx, 31);
        if (cum + tot >= target) {
            unsigned bal = __ballot_sync(0xffffffffu, cum + pfx >= target);
            const int sel = __ffs(bal) - 1;
            B = base + 31 - sel;
            cA = cum + __shfl_sync(0xffffffffu, pfx, sel)
                     - __shfl_sync(0xffffffffu, h, sel);   // strictly above bin B
            break;
        }
        cum += tot;
    }
    if (B < 0) cA = cum;
    if (lane == 0) { *s_B = B; *s_cA = cA; }
}

// Warp 0: exact top-`need` of boundary keys (small sets only).
__device__ __forceinline__ void bnd_select(unsigned long long* bnd, int nb, int need,
                                           unsigned long long* out, int lane) {
    for (int r = 0; r < need; r++) {
        unsigned long long lm = 0ull; int li = 0;
        for (int i = lane; i < nb; i += 32) {
            unsigned long long k = bnd[i];
            if (k > lm) { lm = k; li = i; }
        }
#pragma unroll
        for (int off = 16; off; off >>= 1) {
            unsigned long long ok = __shfl_down_sync(0xffffffffu, lm, off);
            int oi = __shfl_down_sync(0xffffffffu, li, off);
            if (ok > lm) { lm = ok; li = oi; }
        }
        if (lane == 0) { out[r] = lm; bnd[li] = 0ull; }
        __syncwarp();
    }
}

// ---------------------------------------------------------------------------
// Strip pipeline: separable 5x5 conv + 3x3 maxpool peak test, all state in
// registers; horizontal taps/max via warp shuffles. EDGE=false drops the
// per-row -inf-pad selects (valid for interior strips). Prefetch guard
// pr<=rmax_eff self-masks the final RING block (no tail code).
// ---------------------------------------------------------------------------
template<bool EDGE>
__device__ __forceinline__ void strip_loop(
    const float* __restrict__ heat, int r0, int col, bool col_in,
    bool out_lane, int lane,
    float rw0, float rw1, float rw2, float rw3, float rw4,
    float cw0, float cw1, float cw3, float cw4,
    unsigned long long* s_buf, int* s_hist, int* s_cnt)
{
    const float NEG = -3.402823466e38f;
    const int rmax_eff = min(r0 + STRIPH + 2, HH - 1);

    float vb[RING];
#pragma unroll
    for (int j = 0; j < RING; j++) {
        const int r = r0 - 3 + j;
        float nv = 0.f;
        if (col_in && r >= 0 && r <= rmax_eff) nv = __ldg(&heat[r * WW + col]);
        vb[j] = nv;
    }

    float h0 = 0, h1 = 0, h2 = 0, h3 = 0, h4 = 0;   // h-conv ring (5 rows)
    float sA = 0, sB = 0, sC = 0;                   // smoothed ring (3 rows)
    float p0 = 0, p1 = 0, p2 = 0;                   // raw ring (3 rows)

    for (int rb = 0; rb < PITER; rb += RING) {
#pragma unroll
        for (int u = 0; u < RING; u++) {
            const int ri = rb + u;
            const float v = vb[u];
            {   // prefetch row gr+RING into the consumed slot (auto-masked at tail)
                const int pr = r0 - 3 + ri + RING;
                float nv = 0.f;
                if (col_in && pr <= rmax_eff) nv = __ldg(&heat[pr * WW + col]);
                vb[u] = nv;
            }
            // horizontal 5-tap (column col+d lives on lane+d)
            const float a  = __shfl_sync(0xffffffffu, v, lane - 2);
            const float b  = __shfl_sync(0xffffffffu, v, lane - 1);
            const float c2 = __shfl_sync(0xffffffffu, v, lane + 1);
            const float d  = __shfl_sync(0xffffffffu, v, lane + 2);
            const float hs = rw0 * a + rw1 * b + rw2 * v + rw3 * c2 + rw4 * d;
            h0 = h1; h1 = h2; h2 = h3; h3 = h4; h4 = hs;
            // vertical 5-tap -> smoothed at row m = gr-2
            const float sm = cw0 * h0 + cw1 * h1 + h2 + cw3 * h3 + cw4 * h4;
            sA = sB; sB = sC; sC = sm;
            // vertical 3-max over rows m-2..m, centered at t = m-1
            float vm;
            if (EDGE) {
                const int m = r0 - 5 + ri;
                const float fa = (m - 2 >= 0) ? sA : NEG;
                const float fb = ((unsigned)(m - 1) < (unsigned)HH) ? sB : NEG;
                const float fc = ((unsigned)m < (unsigned)HH) ? sC : NEG;
                vm = fmaxf(fa, fmaxf(fb, fc));
            } else {
                vm = fmaxf(sA, fmaxf(sB, sC));
            }
            const float vmL = __shfl_sync(0xffffffffu, vm, lane - 1);
            const float vmR = __shfl_sync(0xffffffffu, vm, lane + 1);
            const float raw = p0;                   // raw heat at row t = gr-3
            p0 = p1; p1 = p2; p2 = v;

            bool peak = false;
            unsigned long long key = 0ull;
            if ((unsigned)(ri - 6) < (unsigned)STRIPH && out_lane) {
                float wmax = vm;                    // includes center: >= test == equality
                if (col > 0)      wmax = fmaxf(wmax, vmL);
                if (col < WW - 1) wmax = fmaxf(wmax, vmR);
                if (sB >= wmax && raw > NMS_T) {    // sB = smoothed at row t; raw=0 past HH
                    peak = true;
                    const unsigned idx = (unsigned)((r0 + ri - 6) * WW + col);
                    key = ((unsigned long long)__float_as_uint(raw) << 32)
                          | (0xFFFFFFFFu - idx);
                }
            }
            const unsigned msk = __ballot_sync(0xffffffffu, peak);
            if (peak) {
                const int leader = __ffs(msk) - 1;
                const int rank = __popc(msk & ((1u << lane) - 1u));
                int pb = 0;
                if (lane == leader) pb = atomicAdd(s_cnt, __popc(msk));
                pb = __shfl_sync(msk, pb, leader);
                const int p = pb + rank;
                if (p < CAPB) {
                    s_buf[p] = key;
                    atomicAdd(&s_hist[keybin(key)], 1);
                }
            }
        }
    }
}

// ---------------------------------------------------------------------------
// Kernel A: strips -> peak candidates -> histogram-threshold block top-50
// superset -> fixed 64-slot global slice (zero padded). Block-level boundary
// bins hold ~3 keys (threshold sits mid-distribution), so 1 level suffices.
// ---------------------------------------------------------------------------
__global__ void __launch_bounds__(256) peaks_kernel(const float* __restrict__ heat,
                                                    const float* __restrict__ kk)
{
    __shared__ unsigned long long s_buf[CAPB];
    __shared__ int s_hist[NBINS];
    __shared__ unsigned long long s_bnd[BND];
    __shared__ unsigned long long s_out[SLOTS];
    __shared__ int s_cnt, s_ctrD, s_ctrB, s_B, s_cA;

    const int tid = threadIdx.x, lane = tid & 31, wid = tid >> 5;
    for (int i = tid; i < NBINS; i += 256) s_hist[i] = 0;
    if (tid < SLOTS) s_out[tid] = 0ull;
    if (tid == 0) { s_cnt = 0; s_ctrD = 0; s_ctrB = 0; }
    __syncthreads();

    const int s = blockIdx.x * WPB + wid;       // s >= NSTRIP -> inert (loads masked)
    const int sx = s % SX, sy = s / SX;
    const int col = sx * OUTC + lane - 3;
    const bool col_in = (unsigned)col < (unsigned)WW;
    const int r0 = sy * STRIPH;
    const bool out_lane = (lane >= 3) && (lane <= 28) && col_in;

    // rank-1 factorization: k[i][j] = (k[i][2]/k[2][2]) * k[2][j]
    const float rw0 = kk[10], rw1 = kk[11], rw2 = kk[12], rw3 = kk[13], rw4 = kk[14];
    const float inv = 1.0f / kk[12];
    const float cw0 = kk[2] * inv, cw1 = kk[7] * inv, cw3 = kk[17] * inv, cw4 = kk[22] * inv;

    const bool edge = (r0 < 3) || (r0 + STRIPH + 2 >= HH);
    if (edge)
        strip_loop<true >(heat, r0, col, col_in, out_lane, lane,
                          rw0, rw1, rw2, rw3, rw4, cw0, cw1, cw3, cw4,
                          s_buf, s_hist, &s_cnt);
    else
        strip_loop<false>(heat, r0, col, col_in, out_lane, lane,
                          rw0, rw1, rw2, rw3, rw4, cw0, cw1, cw3, cw4,
                          s_buf, s_hist, &s_cnt);

    __syncthreads();
    if (wid == 0) find_thresh(s_hist, lane, KTOP, &s_B, &s_cA);
    __syncthreads();
    const int B = s_B;
    const int cnt = min(s_cnt, CAPB);
    for (int i = tid; i < cnt; i += 256) {
        const unsigned long long k = s_buf[i];
        const int b = keybin(k);
        if (B < 0 || b > B) {                       // definite member of block top-50
            const int p = atomicAdd(&s_ctrD, 1);
            if (p < SLOTS) s_out[p] = k;
        } else if (b == B) {                        // boundary bin
            const int p = atomicAdd(&s_ctrB, 1);
            if (p < BND) s_bnd[p] = k;
        }
    }
    __syncthreads();
    const int c = s_ctrD;                           // < KTOP when B >= 0
    const int nb = min(s_ctrB, BND);
    if (B >= 0) {
        if (c + nb <= SLOTS) {                      // common: superset fits
            if (tid < nb) s_out[c + tid] = s_bnd[tid];
        } else if (wid == 0) {                      // rare exact fallback
            bnd_select(s_bnd, nb, KTOP - c, s_out + c, lane);
        }
    }
    __syncthreads();
    if (tid < SLOTS) g_cand[blockIdx.x * SLOTS + tid] = s_out[tid];
}

// ---------------------------------------------------------------------------
// Kernel B: exact global top-50 over 8896 keys. TWO-LEVEL histogram: the
// coarse bin near value 1.0 is ~0.002 wide and holds ~430 keys (the R3 bug:
// it overflowed the 256-slot boundary buffer). Level 2 re-bins the boundary
// bin by the next 11 float bits (16 ulp), shrinking the boundary to ~1-3 keys
// before the exact merge + rank sort. Then the gather epilogue.
// Output (f32, 500): scores[50] | classids[50] | pos[50,3] | dim[50,3]
//                  | angles[50] | valid[50]
// ---------------------------------------------------------------------------
__global__ void __launch_bounds__(256) final_kernel(
    const float* __restrict__ pos_off, const float* __restrict__ dim_off,
    const float* __restrict__ ang_off, const float* __restrict__ grid,
    float* __restrict__ out)
{
    __shared__ int s_hist[NBINS];
    __shared__ unsigned long long s_win[KTOP];
    __shared__ unsigned long long s_bnd[256];
    __shared__ unsigned long long s_sorted[KTOP];
    __shared__ int s_ctrD, s_ctrB, s_B1, s_cA1, s_B2, s_cA2, s_nt;

    const int tid = threadIdx.x, lane = tid & 31, wid = tid >> 5;
    for (int i = tid; i < NBINS; i += 256) s_hist[i] = 0;
    if (tid == 0) { s_ctrD = 0; s_ctrB = 0; }
    __syncthreads();

    // level 1: coarse histogram over all candidate keys
    for (int i = tid; i < NG; i += 256) {
        const unsigned long long k = g_cand[i];
        if (k) atomicAdd(&s_hist[keybin(k)], 1);
    }
    __syncthreads();
    if (wid == 0) find_thresh(s_hist, lane, KTOP, &s_B1, &s_cA1);
    __syncthreads();
    const int B1 = s_B1, cA1 = s_cA1;

    int B2 = -1;
    if (B1 >= 0) {
        // level 2: re-bin only bin-B1 keys by the next 11 float bits
        for (int i = tid; i < NBINS; i += 256) s_hist[i] = 0;
        __syncthreads();
        for (int i = tid; i < NG; i += 256) {
            const unsigned long long k = g_cand[i];
            if (k && keybin(k) == B1) atomicAdd(&s_hist[keybin2(k)], 1);
        }
        __syncthreads();
        if (wid == 0) find_thresh(s_hist, lane, KTOP - cA1, &s_B2, &s_cA2);
        __syncthreads();
        B2 = s_B2;                                  // always >= 0 here
    }

    // classify: definite (above threshold pair) vs boundary (tiny set)
    for (int i = tid; i < NG; i += 256) {
        const unsigned long long k = g_cand[i];
        if (!k) continue;
        const int b1 = keybin(k);
        bool def = false, bnd = false;
        if (B1 < 0 || b1 > B1) def = true;
        else if (b1 == B1) {
            const int b2 = keybin2(k);
            if (b2 > B2) def = true;
            else if (b2 == B2) bnd = true;
        }
        if (def) {
            const int p = atomicAdd(&s_ctrD, 1);
            if (p < KTOP) s_win[p] = k;             // count = cA1+cA2 < KTOP guaranteed
        } else if (bnd) {
            const int p = atomicAdd(&s_ctrB, 1);
            if (p < 256) s_bnd[p] = k;
        }
    }
    __syncthreads();
    const int c = s_ctrD;
    const int nb = min(s_ctrB, 256);
    if (B1 < 0) {
        if (tid == 0) s_nt = min(c, KTOP);
    } else {
        const int need = KTOP - c;                  // nb >= need by construction
        if (nb <= need) {
            if (tid < nb) s_win[c + tid] = s_bnd[tid];
            if (tid == 0) s_nt = c + nb;
        } else {
            if (wid == 0) bnd_select(s_bnd, nb, need, s_win + c, lane);
            if (tid == 0) s_nt = KTOP;
        }
    }
    __syncthreads();
    const int nt = s_nt;
    if (tid < nt) {                                 // rank sort (keys unique)
        const unsigned long long k = s_win[tid];
        int rank = 0;
        for (int j = 0; j < nt; j++) rank += (s_win[j] > k);
        s_sorted[rank] = k;
    }
    __syncthreads();

    if (tid < KTOP) {
        const bool valid = tid < nt;
        float score = 0.f, cls = -1.f, px = 0.f, py = 0.f, pz = 0.f;
        float dx = 0.f, dy = 0.f, dz = 0.f, ang = 0.f, vf = 0.f;
        if (valid) {
            const unsigned long long w = s_sorted[tid];
            const unsigned idx = 0xFFFFFFFFu - (unsigned)(w & 0xFFFFFFFFull);
            const int hh = idx / WW, ww = idx % WW;
            score = __uint_as_float((unsigned)(w >> 32));
            cls = 0.0f; vf = 1.0f;

            const int WP = WW + 1;
            const int g0 = (hh * WP + ww) * 3;
            const int g1 = ((hh + 1) * WP + (ww + 1)) * 3;
            const float cx = 0.5f * (grid[g0 + 0] + grid[g1 + 0]);
            const float cy = 0.5f * (grid[g0 + 1] + grid[g1 + 1]);
            const float cz = 0.5f * (grid[g0 + 2] + grid[g1 + 2]);

            const int o = hh * WW + ww;
            px = pos_off[0 * HH * WW + o] * 0.5f  + cx;
            py = pos_off[1 * HH * WW + o] * 0.36f + cy;
            pz = pos_off[2 * HH * WW + o] * 0.5f  + cz;
            dx = expf(dim_off[0 * HH * WW + o] * 0.085f + 0.42f);
            dy = expf(dim_off[1 * HH * WW + o] * 0.067f + 0.48f);
            dz = expf(dim_off[2 * HH * WW + o] * 0.115f + 1.35f);
            ang = atan2f(ang_off[1 * HH * WW + o], ang_off[0 * HH * WW + o]);
        }
        out[tid]           = score;
        out[50 + tid]      = cls;
        out[100 + 3 * tid] = px;
        out[101 + 3 * tid] = py;
        out[102 + 3 * tid] = pz;
        out[250 + 3 * tid] = dx;
        out[251 + 3 * tid] = dy;
        out[252 + 3 * tid] = dz;
        out[400 + tid]     = ang;
        out[450 + tid]     = vf;
    }
}

extern "C" void kernel_launch(void* const* d_in, const int* in_sizes, int n_in,
                              void* d_out, int out_size)
{
    const float* heat = (const float*)d_in[0];
    const float* pos  = (const float*)d_in[1];
    const float* dim  = (const float*)d_in[2];
    const float* ang  = (const float*)d_in[3];
    const float* grid = (const float*)d_in[4];
    const float* kk   = (const float*)d_in[5];
    float* out = (float*)d_out;

    peaks_kernel<<<NBLK, 256>>>(heat, kk);
    final_kernel<<<1, 256>>>(pos, dim, ang, grid, out);
}

// round 10
// speedup vs baseline: 1.3480x; 1.3480x over previous
#include <cuda_runtime.h>
#include <math.h>

// Fixed problem: C=1, H=W=2048
#define HH 2048
#define WW 2048
#define NMS_T 0.05f
#define KTOP 50

// 2px/lane geometry: lane holds an even float2 column pair. Warp reads 64
// cols (halo 4+4), outputs 56 (lanes 2..29, both components). Strips:
// 37 x 32 = 1184 = 148 blocks x 8 warps -> exact single wave, no inert warps.
#define OUTW 56
#define SX2 37
#define SY2 32
#define STRIPH2 64
#define WPB 8
#define NBLK2 148
#define SLOTS 64            // per-block output slice (superset of block top-50)
#define NG (NBLK2*SLOTS)    // 9472 keys = 74KB (final_kernel dynamic smem)

#define CAPB 4352           // per-block candidate buffer (expected ~1450 peaks)
#define NBINS 2048
#define BINBASE 31385       // float_bits(0.05f) >> 15
#define BND 192
#define RING 8              // float2 prefetch ring: 8 x 8 warps x 256B = 16KB/SM in flight
#define PITER2 72           // 9*RING >= STRIPH2+6

__device__ unsigned long long g_cand[NG];

// key = (float_bits(raw) << 32) | (~idx): descending key order == lax.top_k
// order (value desc, ties -> lower flat index). bin1 monotone in key.
__device__ __forceinline__ int keybin(unsigned long long k) {
    int b = (int)(k >> 47) - BINBASE;
    return b < 0 ? 0 : (b > NBINS - 1 ? NBINS - 1 : b);
}
// level-2 sub-bin: next 11 float bits (16-ulp granularity) within a bin1.
__device__ __forceinline__ int keybin2(unsigned long long k) {
    return (int)((unsigned)(k >> 36) & 0x7FFu);
}

// Warp 0: scan histogram top-down; find bin B with cum(>B) < target <= cum(>=B).
// Also returns cA = cum(>B). B = -1 (cA = total) if total < target.
__device__ __forceinline__ void find_thresh(const int* hist, int lane, int target,
                                            int* s_B, int* s_cA) {
    int cum = 0, B = -1, cA = 0;
    for (int base = NBINS - 32; base >= 0; base -= 32) {
        int h = hist[base + 31 - lane];
        int pfx = h;
#pragma unroll
        for (int off = 1; off < 32; off <<= 1) {
            int o = __shfl_up_sync(0xffffffffu, pfx, off);
            if (lane >= off) pfx += o;
        }
        int tot = __shfl_sync(0xffffffffu, pfx, 31);
        if (cum + tot >= target) {
            unsigned bal = __ballot_sync(0xffffffffu, cum + pfx >= target);
            const int sel = __ffs(bal) - 1;
            B = base + 31 - sel;
            cA = cum + __shfl_sync(0xffffffffu, pfx, sel)
                     - __shfl_sync(0xffffffffu, h, sel);
            break;
        }
        cum += tot;
    }
    if (B < 0) cA = cum;
    if (lane == 0) { *s_B = B; *s_cA = cA; }
}

// Warp 0: exact top-`need` of boundary keys (small sets only).
__device__ __forceinline__ void bnd_select(unsigned long long* bnd, int nb, int need,
                                           unsigned long long* out, int lane) {
    for (int r = 0; r < need; r++) {
        unsigned long long lm = 0ull; int li = 0;
        for (int i = lane; i < nb; i += 32) {
            unsigned long long k = bnd[i];
            if (k > lm) { lm = k; li = i; }
        }
#pragma unroll
        for (int off = 16; off; off >>= 1) {
            unsigned long long ok = __shfl_down_sync(0xffffffffu, lm, off);
            int oi = __shfl_down_sync(0xffffffffu, li, off);
            if (ok > lm) { lm = ok; li = oi; }
        }
        if (lane == 0) { out[r] = lm; bnd[li] = 0ull; }
        __syncwarp();
    }
}

// ---------------------------------------------------------------------------
// 2px/lane strip pipeline. All conv/max state in float2 registers; neighbor
// taps via 4 shuffles/row, vm neighbors via 2 shuffles/row. EDGE template
// drops per-row -inf-pad selects for interior strips.
// ---------------------------------------------------------------------------
template<bool EDGE>
__device__ __forceinline__ void strip_loop2(
    const float* __restrict__ heat, int r0, int c0, bool lane_in,
    bool out_lane, int lane,
    float rw0, float rw1, float rw2, float rw3, float rw4,
    float cw0, float cw1, float cw3, float cw4,
    unsigned long long* s_buf, int* s_hist, int* s_cnt)
{
    const float NEG = -3.402823466e38f;
    const int rmax_eff = min(r0 + STRIPH2 + 2, HH - 1);
    const unsigned FULL = 0xffffffffu;

    float2 vb[RING];
#pragma unroll
    for (int j = 0; j < RING; j++) {
        const int r = r0 - 3 + j;
        float2 nv = make_float2(0.f, 0.f);
        if (lane_in && r >= 0 && r <= rmax_eff)
            nv = *reinterpret_cast<const float2*>(heat + r * WW + c0);
        vb[j] = nv;
    }

    float2 h0 = {0,0}, h1 = {0,0}, h2 = {0,0}, h3 = {0,0}, h4 = {0,0};
    float2 sA = {0,0}, sB = {0,0}, sC = {0,0};
    float2 p0 = {0,0}, p1 = {0,0}, p2 = {0,0};
    const int c1 = c0 + 1;

    for (int rb = 0; rb < PITER2; rb += RING) {
#pragma unroll
        for (int u = 0; u < RING; u++) {
            const int ri = rb + u;
            const float2 v = vb[u];
            {   // prefetch row gr+RING into consumed slot (auto-masked at tail;
                // pr = r0-3+ri+RING >= 5, so no lower guard needed)
                const int pr = r0 - 3 + ri + RING;
                float2 nv = make_float2(0.f, 0.f);
                if (lane_in && pr <= rmax_eff)
                    nv = *reinterpret_cast<const float2*>(heat + pr * WW + c0);
                vb[u] = nv;
            }
            // neighbor pairs: lane-1 holds cols c0-2,c0-1; lane+1 holds c0+2,c0+3
            const float pmx = __shfl_sync(FULL, v.x, lane - 1);
            const float pmy = __shfl_sync(FULL, v.y, lane - 1);
            const float npx = __shfl_sync(FULL, v.x, lane + 1);
            const float npy = __shfl_sync(FULL, v.y, lane + 1);
            // horizontal 5-tap, both columns
            const float hsx = rw0*pmx + rw1*pmy + rw2*v.x + rw3*v.y + rw4*npx;
            const float hsy = rw0*pmy + rw1*v.x + rw2*v.y + rw3*npx + rw4*npy;
            h0 = h1; h1 = h2; h2 = h3; h3 = h4; h4 = make_float2(hsx, hsy);
            // vertical 5-tap -> smoothed at row m = gr-2 (cw2 == 1)
            const float smx = cw0*h0.x + cw1*h1.x + h2.x + cw3*h3.x + cw4*h4.x;
            const float smy = cw0*h0.y + cw1*h1.y + h2.y + cw3*h3.y + cw4*h4.y;
            sA = sB; sB = sC; sC = make_float2(smx, smy);
            // vertical 3-max over rows m-2..m, centered at t = m-1
            float vmx, vmy;
            if (EDGE) {
                const int m = r0 - 5 + ri;
                const bool gA = (m - 2) >= 0;
                const bool gB = (unsigned)(m - 1) < (unsigned)HH;
                const bool gC = (unsigned)m < (unsigned)HH;
                vmx = fmaxf(gA ? sA.x : NEG, fmaxf(gB ? sB.x : NEG, gC ? sC.x : NEG));
                vmy = fmaxf(gA ? sA.y : NEG, fmaxf(gB ? sB.y : NEG, gC ? sC.y : NEG));
            } else {
                vmx = fmaxf(sA.x, fmaxf(sB.x, sC.x));
                vmy = fmaxf(sA.y, fmaxf(sB.y, sC.y));
            }
            const float prev_vm1 = __shfl_sync(FULL, vmy, lane - 1);  // vm(c0-1)
            const float next_vm0 = __shfl_sync(FULL, vmx, lane + 1);  // vm(c1+1)
            const float2 raw = p0;                  // raw heat at row t = gr-3
            p0 = p1; p1 = p2; p2 = v;

            bool pk0 = false, pk1 = false;
            unsigned long long k0 = 0ull, k1 = 0ull;
            if ((unsigned)(ri - 6) < (unsigned)STRIPH2 && out_lane) {
                // wmax includes center (>= test == equality with window max)
                float w0 = fmaxf(vmx, vmy);         // vm(c0), vm(c0+1)
                if (c0 > 0) w0 = fmaxf(w0, prev_vm1);
                float w1 = fmaxf(vmx, vmy);         // vm(c1-1), vm(c1)
                if (c1 < WW - 1) w1 = fmaxf(w1, next_vm0);
                const int t = r0 + ri - 6;
                if (sB.x >= w0 && raw.x > NMS_T) {  // raw=0 for unloaded cols
                    pk0 = true;
                    const unsigned idx = (unsigned)(t * WW + c0);
                    k0 = ((unsigned long long)__float_as_uint(raw.x) << 32)
                         | (0xFFFFFFFFu - idx);
                }
                if (sB.y >= w1 && raw.y > NMS_T) {
                    pk1 = true;
                    const unsigned idx = (unsigned)(t * WW + c1);
                    k1 = ((unsigned long long)__float_as_uint(raw.y) << 32)
                         | (0xFFFFFFFFu - idx);
                }
            }
            const unsigned m0 = __ballot_sync(FULL, pk0);
            const unsigned m1 = __ballot_sync(FULL, pk1);
            if (m0 | m1) {                          // warp-uniform
                const int tot = __popc(m0) + __popc(m1);
                int pb = 0;
                if (lane == 0) pb = atomicAdd(s_cnt, tot);
                pb = __shfl_sync(FULL, pb, 0);
                const unsigned lt = (1u << lane) - 1u;
                if (pk0) {
                    const int p = pb + __popc(m0 & lt);
                    if (p < CAPB) { s_buf[p] = k0; atomicAdd(&s_hist[keybin(k0)], 1); }
                }
                if (pk1) {
                    const int p = pb + __popc(m0) + __popc(m1 & lt);
                    if (p < CAPB) { s_buf[p] = k1; atomicAdd(&s_hist[keybin(k1)], 1); }
                }
            }
        }
    }
}

// ---------------------------------------------------------------------------
// Kernel A: strips -> peaks -> histogram-threshold block top-50 superset ->
// fixed 64-slot global slice (zero padded).
// ---------------------------------------------------------------------------
__global__ void __launch_bounds__(256) peaks_kernel(const float* __restrict__ heat,
                                                    const float* __restrict__ kk)
{
    __shared__ unsigned long long s_buf[CAPB];
    __shared__ int s_hist[NBINS];
    __shared__ unsigned long long s_bnd[BND];
    __shared__ unsigned long long s_out[SLOTS];
    __shared__ int s_cnt, s_ctrD, s_ctrB, s_B, s_cA;

    const int tid = threadIdx.x, lane = tid & 31, wid = tid >> 5;
    for (int i = tid; i < NBINS; i += 256) s_hist[i] = 0;
    if (tid < SLOTS) s_out[tid] = 0ull;
    if (tid == 0) { s_cnt = 0; s_ctrD = 0; s_ctrB = 0; }
    __syncthreads();

    const int s = blockIdx.x * WPB + wid;           // 0..1183, exact fit
    const int sx = s % SX2, sy = s / SX2;
    const int c0 = sx * OUTW - 4 + 2 * lane;        // even
    const bool lane_in = (c0 >= 0) && (c0 < WW);    // c1=c0+1 < WW too (c0 even)
    const int r0 = sy * STRIPH2;
    const bool out_lane = (lane >= 2) && (lane <= 29);

    // rank-1 factorization: k[i][j] = (k[i][2]/k[2][2]) * k[2][j]
    const float rw0 = kk[10], rw1 = kk[11], rw2 = kk[12], rw3 = kk[13], rw4 = kk[14];
    const float inv = 1.0f / kk[12];
    const float cw0 = kk[2] * inv, cw1 = kk[7] * inv, cw3 = kk[17] * inv, cw4 = kk[22] * inv;

    const bool edge = (r0 < 3) || (r0 + STRIPH2 + 2 >= HH);
    if (edge)
        strip_loop2<true >(heat, r0, c0, lane_in, out_lane, lane,
                           rw0, rw1, rw2, rw3, rw4, cw0, cw1, cw3, cw4,
                           s_buf, s_hist, &s_cnt);
    else
        strip_loop2<false>(heat, r0, c0, lane_in, out_lane, lane,
                           rw0, rw1, rw2, rw3, rw4, cw0, cw1, cw3, cw4,
                           s_buf, s_hist, &s_cnt);

    __syncthreads();
    if (wid == 0) find_thresh(s_hist, lane, KTOP, &s_B, &s_cA);
    __syncthreads();
    const int B = s_B;
    const int cnt = min(s_cnt, CAPB);
    for (int i = tid; i < cnt; i += 256) {
        const unsigned long long k = s_buf[i];
        const int b = keybin(k);
        if (B < 0 || b > B) {                       // definite member of block top-50
            const int p = atomicAdd(&s_ctrD, 1);
            if (p < SLOTS) s_out[p] = k;
        } else if (b == B) {                        // boundary bin
            const int p = atomicAdd(&s_ctrB, 1);
            if (p < BND) s_bnd[p] = k;
        }
    }
    __syncthreads();
    const int c = s_ctrD;                           // < KTOP when B >= 0
    const int nb = min(s_ctrB, BND);
    if (B >= 0) {
        if (c + nb <= SLOTS) {                      // common: superset fits
            if (tid < nb) s_out[c + tid] = s_bnd[tid];
        } else if (wid == 0) {                      // rare exact fallback
            bnd_select(s_bnd, nb, KTOP - c, s_out + c, lane);
        }
    }
    __syncthreads();
    if (tid < SLOTS) g_cand[blockIdx.x * SLOTS + tid] = s_out[tid];
}

// ---------------------------------------------------------------------------
// Kernel B: stage all NG keys into dynamic shared ONCE (fused with level-1
// histogram), then two-level threshold + exact boundary merge + rank sort
// entirely in smem, then the gather epilogue. R8 profile showed this kernel
// 23.4us latency-bound on repeated global passes (DRAM=0.1%, issue=13%).
// Output (f32, 500): scores[50] | classids[50] | pos[50,3] | dim[50,3]
//                  | angles[50] | valid[50]
// ---------------------------------------------------------------------------
__global__ void __launch_bounds__(256) final_kernel(
    const float* __restrict__ pos_off, const float* __restrict__ dim_off,
    const float* __restrict__ ang_off, const float* __restrict__ grid,
    float* __restrict__ out)
{
    extern __shared__ unsigned long long s_k[];     // NG keys (74KB dynamic)
    __shared__ int s_hist[NBINS];
    __shared__ unsigned long long s_win[KTOP];
    __shared__ unsigned long long s_bnd[256];
    __shared__ unsigned long long s_sorted[KTOP];
    __shared__ int s_ctrD, s_ctrB, s_B1, s_cA1, s_B2, s_cA2, s_nt;

    const int tid = threadIdx.x, lane = tid & 31, wid = tid >> 5;
    for (int i = tid; i < NBINS; i += 256) s_hist[i] = 0;
    if (tid == 0) { s_ctrD = 0; s_ctrB = 0; }
    __syncthreads();

    // single global pass: stage keys + level-1 histogram
    for (int i = tid; i < NG; i += 256) {
        const unsigned long long k = g_cand[i];
        s_k[i] = k;
        if (k) atomicAdd(&s_hist[keybin(k)], 1);
    }
    __syncthreads();
    if (wid == 0) find_thresh(s_hist, lane, KTOP, &s_B1, &s_cA1);
    __syncthreads();
    const int B1 = s_B1, cA1 = s_cA1;

    int B2 = -1;
    if (B1 >= 0) {
        // level 2: re-bin only bin-B1 keys by the next 11 float bits (smem)
        for (int i = tid; i < NBINS; i += 256) s_hist[i] = 0;
        __syncthreads();
        for (int i = tid; i < NG; i += 256) {
            const unsigned long long k = s_k[i];
            if (k && keybin(k) == B1) atomicAdd(&s_hist[keybin2(k)], 1);
        }
        __syncthreads();
        if (wid == 0) find_thresh(s_hist, lane, KTOP - cA1, &s_B2, &s_cA2);
        __syncthreads();
        B2 = s_B2;                                  // always >= 0 here
    }

    // classify from smem: definite vs boundary (tiny set)
    for (int i = tid; i < NG; i += 256) {
        const unsigned long long k = s_k[i];
        if (!k) continue;
        const int b1 = keybin(k);
        bool def = false, bnd = false;
        if (B1 < 0 || b1 > B1) def = true;
        else if (b1 == B1) {
            const int b2 = keybin2(k);
            if (b2 > B2) def = true;
            else if (b2 == B2) bnd = true;
        }
        if (def) {
            const int p = atomicAdd(&s_ctrD, 1);
            if (p < KTOP) s_win[p] = k;             // count = cA1+cA2 < KTOP guaranteed
        } else if (bnd) {
            const int p = atomicAdd(&s_ctrB, 1);
            if (p < 256) s_bnd[p] = k;
        }
    }
    __syncthreads();
    const int c = s_ctrD;
    const int nb = min(s_ctrB, 256);
    if (B1 < 0) {
        if (tid == 0) s_nt = min(c, KTOP);
    } else {
        const int need = KTOP - c;                  // nb >= need by construction
        if (nb <= need) {
            if (tid < nb) s_win[c + tid] = s_bnd[tid];
            if (tid == 0) s_nt = c + nb;
        } else {
            if (wid == 0) bnd_select(s_bnd, nb, need, s_win + c, lane);
            if (tid == 0) s_nt = KTOP;
        }
    }
    __syncthreads();
    const int nt = s_nt;
    if (tid < nt) {                                 // rank sort (keys unique)
        const unsigned long long k = s_win[tid];
        int rank = 0;
        for (int j = 0; j < nt; j++) rank += (s_win[j] > k);
        s_sorted[rank] = k;
    }
    __syncthreads();

    if (tid < KTOP) {
        const bool valid = tid < nt;
        float score = 0.f, cls = -1.f, px = 0.f, py = 0.f, pz = 0.f;
        float dx = 0.f, dy = 0.f, dz = 0.f, ang = 0.f, vf = 0.f;
        if (valid) {
            const unsigned long long w = s_sorted[tid];
            const unsigned idx = 0xFFFFFFFFu - (unsigned)(w & 0xFFFFFFFFull);
            const int hh = idx / WW, ww = idx % WW;
            score = __uint_as_float((unsigned)(w >> 32));
            cls = 0.0f; vf = 1.0f;

            const int WP = WW + 1;
            const int g0 = (hh * WP + ww) * 3;
            const int g1 = ((hh + 1) * WP + (ww + 1)) * 3;
            const float cx = 0.5f * (grid[g0 + 0] + grid[g1 + 0]);
            const float cy = 0.5f * (grid[g0 + 1] + grid[g1 + 1]);
            const float cz = 0.5f * (grid[g0 + 2] + grid[g1 + 2]);

            const int o = hh * WW + ww;
            px = pos_off[0 * HH * WW + o] * 0.5f  + cx;
            py = pos_off[1 * HH * WW + o] * 0.36f + cy;
            pz = pos_off[2 * HH * WW + o] * 0.5f  + cz;
            dx = expf(dim_off[0 * HH * WW + o] * 0.085f + 0.42f);
            dy = expf(dim_off[1 * HH * WW + o] * 0.067f + 0.48f);
            dz = expf(dim_off[2 * HH * WW + o] * 0.115f + 1.35f);
            ang = atan2f(ang_off[1 * HH * WW + o], ang_off[0 * HH * WW + o]);
        }
        out[tid]           = score;
        out[50 + tid]      = cls;
        out[100 + 3 * tid] = px;
        out[101 + 3 * tid] = py;
        out[102 + 3 * tid] = pz;
        out[250 + 3 * tid] = dx;
        out[251 + 3 * tid] = dy;
        out[252 + 3 * tid] = dz;
        out[400 + tid]     = ang;
        out[450 + tid]     = vf;
    }
}

extern "C" void kernel_launch(void* const* d_in, const int* in_sizes, int n_in,
                              void* d_out, int out_size)
{
    const float* heat = (const float*)d_in[0];
    const float* pos  = (const float*)d_in[1];
    const float* dim  = (const float*)d_in[2];
    const float* ang  = (const float*)d_in[3];
    const float* grid = (const float*)d_in[4];
    const float* kk   = (const float*)d_in[5];
    float* out = (float*)d_out;

    // >48KB dynamic smem needs opt-in (host attribute; idempotent; no alloc,
    // not a stream op — safe under graph capture).
    cudaFuncSetAttribute(final_kernel, cudaFuncAttributeMaxDynamicSharedMemorySize,
                         NG * (int)sizeof(unsigned long long));

    peaks_kernel<<<NBLK2, 256>>>(heat, kk);
    final_kernel<<<1, 256, NG * sizeof(unsigned long long)>>>(pos, dim, ang, grid, out);
}

// round 12
// speedup vs baseline: 2.4547x; 1.8210x over previous
#include <cuda_runtime.h>
#include <math.h>

// Fixed problem: C=1, H=W=2048
#define HH 2048
#define WW 2048
#define NMS_T 0.05f
#define KTOP 50

// 2px/lane, 56-col x 16-row strips: 37 x 128 = 4736 strips = 148 blocks x 32 warps.
// 1024-thread blocks -> 32 warps/SM (occ 50%), single wave, NG unchanged.
#define OUTW 56
#define SX2 37
#define SY2 128
#define STRIPH2 16
#define WPB2 32
#define NBLK2 148
#define SLOTS 64            // per-block output slice (superset of block top-50)
#define NG (NBLK2*SLOTS)    // 9472 keys = 74KB (final_kernel dynamic smem)

#define WCAP 144            // per-warp segment (expected ~46 peaks, 3x margin)
#define NSEG (WPB2*WCAP)    // 4608 slots = 36KB
#define NBINS 2048
#define BINBASE 31385       // float_bits(0.05f) >> 15
#define BND 192
#define RING 6              // float2 prefetch ring; 32 warps x 6 x 256B = 48KB/SM in flight
#define PITER2 24           // 4*RING >= STRIPH2+6 rows

__device__ unsigned long long g_cand[NG];

// key = (float_bits(raw) << 32) | (~idx): descending key order == lax.top_k
// order (value desc, ties -> lower flat index). bin1 monotone in key.
__device__ __forceinline__ int keybin(unsigned long long k) {
    int b = (int)(k >> 47) - BINBASE;
    return b < 0 ? 0 : (b > NBINS - 1 ? NBINS - 1 : b);
}
// level-2 sub-bin: next 11 float bits (16-ulp granularity) within a bin1.
__device__ __forceinline__ int keybin2(unsigned long long k) {
    return (int)((unsigned)(k >> 36) & 0x7FFu);
}

// Warp 0: scan histogram top-down from startbin's chunk; find bin B with
// cum(>B) < target <= cum(>=B). Returns cA = cum(>B). B=-1 if total<target.
// Empty chunks skipped with one ballot.
__device__ __forceinline__ void find_thresh(const int* hist, int lane, int target,
                                            int startbin, int* s_B, int* s_cA) {
    int cum = 0, B = -1, cA = 0;
    int base0 = startbin & ~31;
    if (base0 > NBINS - 32) base0 = NBINS - 32;
    for (int base = base0; base >= 0; base -= 32) {
        int h = hist[base + 31 - lane];          // lane 0 = highest bin of chunk
        if (__ballot_sync(0xffffffffu, h != 0) == 0u) continue;
        int pfx = h;
#pragma unroll
        for (int off = 1; off < 32; off <<= 1) {
            int o = __shfl_up_sync(0xffffffffu, pfx, off);
            if (lane >= off) pfx += o;
        }
        int tot = __shfl_sync(0xffffffffu, pfx, 31);
        if (cum + tot >= target) {
            unsigned bal = __ballot_sync(0xffffffffu, cum + pfx >= target);
            const int sel = __ffs(bal) - 1;
            B = base + 31 - sel;
            cA = cum + __shfl_sync(0xffffffffu, pfx, sel)
                     - __shfl_sync(0xffffffffu, h, sel);   // strictly above bin B
            break;
        }
        cum += tot;
    }
    if (B < 0) cA = cum;
    if (lane == 0) { *s_B = B; *s_cA = cA; }
}

// Warp 0: exact top-`need` of boundary keys (small sets only).
__device__ __forceinline__ void bnd_select(unsigned long long* bnd, int nb, int need,
                                           unsigned long long* out, int lane) {
    for (int r = 0; r < need; r++) {
        unsigned long long lm = 0ull; int li = 0;
        for (int i = lane; i < nb; i += 32) {
            unsigned long long k = bnd[i];
            if (k > lm) { lm = k; li = i; }
        }
#pragma unroll
        for (int off = 16; off; off >>= 1) {
            unsigned long long ok = __shfl_down_sync(0xffffffffu, lm, off);
            int oi = __shfl_down_sync(0xffffffffu, li, off);
            if (ok > lm) { lm = ok; li = oi; }
        }
        if (lane == 0) { out[r] = lm; bnd[li] = 0ull; }
        __syncwarp();
    }
}

// ---------------------------------------------------------------------------
// 2px/lane strip pipeline (16-row strips). Appends to this warp's private
// shared segment with a REGISTER cursor (ballot-derived, warp-uniform) —
// zero atomics in the hot loop. Histogram deferred to a post-pass.
// ---------------------------------------------------------------------------
template<bool EDGE>
__device__ __forceinline__ void strip_loop2(
    const float* __restrict__ heat, int r0, int c0, bool lane_in, bool out_lane,
    int lane,
    float rw0, float rw1, float rw2, float rw3, float rw4,
    float cw0, float cw1, float cw3, float cw4,
    unsigned long long* s_seg)
{
    const float NEG = -3.402823466e38f;
    const int rmax_eff = min(r0 + STRIPH2 + 2, HH - 1);
    const unsigned FULL = 0xffffffffu;

    float2 vb[RING];
#pragma unroll
    for (int j = 0; j < RING; j++) {
        const int r = r0 - 3 + j;
        float2 nv = make_float2(0.f, 0.f);
        if (lane_in && r >= 0 && r <= rmax_eff)
            nv = *reinterpret_cast<const float2*>(heat + r * WW + c0);
        vb[j] = nv;
    }

    float2 h0 = {0,0}, h1 = {0,0}, h2 = {0,0}, h3 = {0,0}, h4 = {0,0};
    float2 sA = {0,0}, sB = {0,0}, sC = {0,0};
    float2 p0 = {0,0}, p1 = {0,0}, p2 = {0,0};
    const int c1 = c0 + 1;
    int wcnt = 0;                                   // warp-uniform register cursor

    for (int rb = 0; rb < PITER2; rb += RING) {
#pragma unroll
        for (int u = 0; u < RING; u++) {
            const int ri = rb + u;
            const float2 v = vb[u];
            {   // prefetch row gr+RING into consumed slot (pr >= r0+3 > 0)
                const int pr = r0 - 3 + ri + RING;
                float2 nv = make_float2(0.f, 0.f);
                if (lane_in && pr <= rmax_eff)
                    nv = *reinterpret_cast<const float2*>(heat + pr * WW + c0);
                vb[u] = nv;
            }
            // neighbor pairs: lane-1 holds c0-2,c0-1; lane+1 holds c0+2,c0+3
            const float pmx = __shfl_sync(FULL, v.x, lane - 1);
            const float pmy = __shfl_sync(FULL, v.y, lane - 1);
            const float npx = __shfl_sync(FULL, v.x, lane + 1);
            const float npy = __shfl_sync(FULL, v.y, lane + 1);
            const float hsx = rw0*pmx + rw1*pmy + rw2*v.x + rw3*v.y + rw4*npx;
            const float hsy = rw0*pmy + rw1*v.x + rw2*v.y + rw3*npx + rw4*npy;
            h0 = h1; h1 = h2; h2 = h3; h3 = h4; h4 = make_float2(hsx, hsy);
            // vertical 5-tap -> smoothed at row m = gr-2 (cw2 == 1)
            const float smx = cw0*h0.x + cw1*h1.x + h2.x + cw3*h3.x + cw4*h4.x;
            const float smy = cw0*h0.y + cw1*h1.y + h2.y + cw3*h3.y + cw4*h4.y;
            sA = sB; sB = sC; sC = make_float2(smx, smy);
            // vertical 3-max over rows m-2..m, centered at t = m-1
            float vmx, vmy;
            if (EDGE) {
                const int m = r0 - 5 + ri;
                const bool gA = (m - 2) >= 0;
                const bool gB = (unsigned)(m - 1) < (unsigned)HH;
                const bool gC = (unsigned)m < (unsigned)HH;
                vmx = fmaxf(gA ? sA.x : NEG, fmaxf(gB ? sB.x : NEG, gC ? sC.x : NEG));
                vmy = fmaxf(gA ? sA.y : NEG, fmaxf(gB ? sB.y : NEG, gC ? sC.y : NEG));
            } else {
                vmx = fmaxf(sA.x, fmaxf(sB.x, sC.x));
                vmy = fmaxf(sA.y, fmaxf(sB.y, sC.y));
            }
            const float prev_vm1 = __shfl_sync(FULL, vmy, lane - 1);  // vm(c0-1)
            const float next_vm0 = __shfl_sync(FULL, vmx, lane + 1);  // vm(c1+1)
            const float2 raw = p0;                  // raw heat at row t = gr-3
            p0 = p1; p1 = p2; p2 = v;

            bool pk0 = false, pk1 = false;
            unsigned long long k0 = 0ull, k1 = 0ull;
            if ((unsigned)(ri - 6) < (unsigned)STRIPH2 && out_lane) {
                float w0 = fmaxf(vmx, vmy);         // window max incl. center
                if (c0 > 0) w0 = fmaxf(w0, prev_vm1);
                float w1 = fmaxf(vmx, vmy);
                if (c1 < WW - 1) w1 = fmaxf(w1, next_vm0);
                const int t = r0 + ri - 6;
                if (sB.x >= w0 && raw.x > NMS_T) {
                    pk0 = true;
                    const unsigned idx = (unsigned)(t * WW + c0);
                    k0 = ((unsigned long long)__float_as_uint(raw.x) << 32)
                         | (0xFFFFFFFFu - idx);
                }
                if (sB.y >= w1 && raw.y > NMS_T) {
                    pk1 = true;
                    const unsigned idx = (unsigned)(t * WW + c1);
                    k1 = ((unsigned long long)__float_as_uint(raw.y) << 32)
                         | (0xFFFFFFFFu - idx);
                }
            }
            const unsigned m0 = __ballot_sync(FULL, pk0);
            const unsigned m1 = __ballot_sync(FULL, pk1);
            if (m0 | m1) {                          // warp-uniform
                const unsigned lt = (1u << lane) - 1u;
                if (pk0) {
                    const int p = wcnt + __popc(m0 & lt);
                    if (p < WCAP) s_seg[p] = k0;
                }
                if (pk1) {
                    const int p = wcnt + __popc(m0) + __popc(m1 & lt);
                    if (p < WCAP) s_seg[p] = k1;
                }
                wcnt += __popc(m0) + __popc(m1);
            }
        }
    }
}

// ---------------------------------------------------------------------------
// Kernel A: 32 strips/block -> per-warp segments -> deferred histogram + max
// key -> exact-start threshold -> block top-50 superset -> 64-slot slice.
// ---------------------------------------------------------------------------
__global__ void __launch_bounds__(1024) peaks_kernel(const float* __restrict__ heat,
                                                     const float* __restrict__ kk)
{
    __shared__ unsigned long long s_buf[NSEG];      // 36KB
    __shared__ int s_hist[NBINS];                   // 8KB
    __shared__ unsigned long long s_bnd[BND];
    __shared__ unsigned long long s_out[SLOTS];
    __shared__ unsigned long long s_maxk;
    __shared__ int s_ctrD, s_ctrB, s_B, s_cA;

    const int tid = threadIdx.x, lane = tid & 31, wid = tid >> 5;
    for (int i = tid; i < NSEG; i += 1024) s_buf[i] = 0ull;
    for (int i = tid; i < NBINS; i += 1024) s_hist[i] = 0;
    if (tid < SLOTS) s_out[tid] = 0ull;
    if (tid == 0) { s_maxk = 0ull; s_ctrD = 0; s_ctrB = 0; }
    __syncthreads();

    const int s = blockIdx.x * WPB2 + wid;          // 0..4735, exact fit
    const int sx = s % SX2, sy = s / SX2;
    const int c0 = sx * OUTW - 4 + 2 * lane;        // even
    const bool lane_in = (c0 >= 0) && (c0 < WW);
    const int r0 = sy * STRIPH2;
    const bool out_lane = (lane >= 2) && (lane <= 29);

    // rank-1 factorization: k[i][j] = (k[i][2]/k[2][2]) * k[2][j]
    const float rw0 = kk[10], rw1 = kk[11], rw2 = kk[12], rw3 = kk[13], rw4 = kk[14];
    const float inv = 1.0f / kk[12];
    const float cw0 = kk[2] * inv, cw1 = kk[7] * inv, cw3 = kk[17] * inv, cw4 = kk[22] * inv;

    unsigned long long* seg = s_buf + wid * WCAP;
    const bool edge = (sy == 0) || (sy == SY2 - 1); // warp-uniform branch
    if (edge)
        strip_loop2<true >(heat, r0, c0, lane_in, out_lane, lane,
                           rw0, rw1, rw2, rw3, rw4, cw0, cw1, cw3, cw4, seg);
    else
        strip_loop2<false>(heat, r0, c0, lane_in, out_lane, lane,
                           rw0, rw1, rw2, rw3, rw4, cw0, cw1, cw3, cw4, seg);

    __syncthreads();
    // deferred histogram + block max key
    unsigned long long lmax = 0ull;
    for (int i = tid; i < NSEG; i += 1024) {
        const unsigned long long k = s_buf[i];
        if (k) {
            atomicAdd(&s_hist[keybin(k)], 1);
            if (k > lmax) lmax = k;
        }
    }
#pragma unroll
    for (int off = 16; off; off >>= 1) {
        unsigned long long o = __shfl_down_sync(0xffffffffu, lmax, off);
        lmax = (o > lmax) ? o : lmax;
    }
    if (lane == 0 && lmax) atomicMax(&s_maxk, lmax);
    __syncthreads();
    if (wid == 0) find_thresh(s_hist, lane, KTOP, keybin(s_maxk), &s_B, &s_cA);
    __syncthreads();
    const int B = s_B;
    for (int i = tid; i < NSEG; i += 1024) {
        const unsigned long long k = s_buf[i];
        if (!k) continue;
        const int b = keybin(k);
        if (B < 0 || b > B) {                       // definite member of block top-50
            const int p = atomicAdd(&s_ctrD, 1);
            if (p < SLOTS) s_out[p] = k;
        } else if (b == B) {                        // boundary bin (~3 keys expected)
            const int p = atomicAdd(&s_ctrB, 1);
            if (p < BND) s_bnd[p] = k;
        }
    }
    __syncthreads();
    const int c = s_ctrD;                           // < KTOP when B >= 0
    const int nb = min(s_ctrB, BND);
    if (B >= 0) {
        if (c + nb <= SLOTS) {                      // common: superset fits
            if (tid < nb) s_out[c + tid] = s_bnd[tid];
        } else if (wid == 0) {                      // rare exact fallback
            bnd_select(s_bnd, nb, KTOP - c, s_out + c, lane);
        }
    }
    __syncthreads();
    if (tid < SLOTS) g_cand[blockIdx.x * SLOTS + tid] = s_out[tid];
}

// ---------------------------------------------------------------------------
// Kernel B: 1024 threads. Stage NG keys into smem once (fused with level-1
// histogram + max-key), two-level exact-start threshold, exact boundary
// merge + rank sort, gather epilogue.
// Output (f32, 500): scores[50] | classids[50] | pos[50,3] | dim[50,3]
//                  | angles[50] | valid[50]
// ---------------------------------------------------------------------------
__global__ void __launch_bounds__(1024) final_kernel(
    const float* __restrict__ pos_off, const float* __restrict__ dim_off,
    const float* __restrict__ ang_off, const float* __restrict__ grid,
    float* __restrict__ out)
{
    extern __shared__ unsigned long long s_k[];     // NG keys (74KB dynamic)
    __shared__ int s_hist[NBINS];
    __shared__ unsigned long long s_win[KTOP];
    __shared__ unsigned long long s_bnd[256];
    __shared__ unsigned long long s_sorted[KTOP];
    __shared__ unsigned long long s_maxk, s_maxk2;
    __shared__ int s_ctrD, s_ctrB, s_B1, s_cA1, s_B2, s_cA2, s_nt;

    const int tid = threadIdx.x, lane = tid & 31, wid = tid >> 5;
    for (int i = tid; i < NBINS; i += 1024) s_hist[i] = 0;
    if (tid == 0) { s_ctrD = 0; s_ctrB = 0; s_maxk = 0ull; s_maxk2 = 0ull; }
    __syncthreads();

    // single global pass: stage keys + level-1 histogram + max key
    unsigned long long lmax = 0ull;
    for (int i = tid; i < NG; i += 1024) {
        const unsigned long long k = g_cand[i];
        s_k[i] = k;
        if (k) {
            atomicAdd(&s_hist[keybin(k)], 1);
            if (k > lmax) lmax = k;
        }
    }
#pragma unroll
    for (int off = 16; off; off >>= 1) {
        unsigned long long o = __shfl_down_sync(0xffffffffu, lmax, off);
        lmax = (o > lmax) ? o : lmax;
    }
    if (lane == 0 && lmax) atomicMax(&s_maxk, lmax);
    __syncthreads();
    if (wid == 0) find_thresh(s_hist, lane, KTOP, keybin(s_maxk), &s_B1, &s_cA1);
    __syncthreads();
    const int B1 = s_B1, cA1 = s_cA1;

    int B2 = -1;
    if (B1 >= 0) {
        // level 2: re-bin only bin-B1 keys by the next 11 float bits
        for (int i = tid; i < NBINS; i += 1024) s_hist[i] = 0;
        __syncthreads();
        unsigned long long lmax2 = 0ull;
        for (int i = tid; i < NG; i += 1024) {
            const unsigned long long k = s_k[i];
            if (k && keybin(k) == B1) {
                atomicAdd(&s_hist[keybin2(k)], 1);
                if (k > lmax2) lmax2 = k;
            }
        }
#pragma unroll
        for (int off = 16; off; off >>= 1) {
            unsigned long long o = __shfl_down_sync(0xffffffffu, lmax2, off);
            lmax2 = (o > lmax2) ? o : lmax2;
        }
        if (lane == 0 && lmax2) atomicMax(&s_maxk2, lmax2);
        __syncthreads();
        if (wid == 0) find_thresh(s_hist, lane, KTOP - cA1, keybin2(s_maxk2),
                                  &s_B2, &s_cA2);
        __syncthreads();
        B2 = s_B2;                                  // always >= 0 here
    }

    // classify: definite vs boundary (tiny set)
    for (int i = tid; i < NG; i += 1024) {
        const unsigned long long k = s_k[i];
        if (!k) continue;
        const int b1 = keybin(k);
        bool def = false, bnd = false;
        if (B1 < 0 || b1 > B1) def = true;
        else if (b1 == B1) {
            const int b2 = keybin2(k);
            if (b2 > B2) def = true;
            else if (b2 == B2) bnd = true;
        }
        if (def) {
            const int p = atomicAdd(&s_ctrD, 1);
            if (p < KTOP) s_win[p] = k;             // count = cA1+cA2 < KTOP guaranteed
        } else if (bnd) {
            const int p = atomicAdd(&s_ctrB, 1);
            if (p < 256) s_bnd[p] = k;
        }
    }
    __syncthreads();
    const int c = s_ctrD;
    const int nb = min(s_ctrB, 256);
    if (B1 < 0) {
        if (tid == 0) s_nt = min(c, KTOP);
    } else {
        const int need = KTOP - c;                  // nb >= need by construction
        if (nb <= need) {
            if (tid < nb) s_win[c + tid] = s_bnd[tid];
            if (tid == 0) s_nt = c + nb;
        } else {
            if (wid == 0) bnd_select(s_bnd, nb, need, s_win + c, lane);
            if (tid == 0) s_nt = KTOP;
        }
    }
    __syncthreads();
    const int nt = s_nt;
    if (tid < nt) {                                 // rank sort (keys unique)
        const unsigned long long k = s_win[tid];
        int rank = 0;
        for (int j = 0; j < nt; j++) rank += (s_win[j] > k);
        s_sorted[rank] = k;
    }
    __syncthreads();

    if (tid < KTOP) {
        const bool valid = tid < nt;
        float score = 0.f, cls = -1.f, px = 0.f, py = 0.f, pz = 0.f;
        float dx = 0.f, dy = 0.f, dz = 0.f, ang = 0.f, vf = 0.f;
        if (valid) {
            const unsigned long long w = s_sorted[tid];
            const unsigned idx = 0xFFFFFFFFu - (unsigned)(w & 0xFFFFFFFFull);
            const int hh = idx / WW, ww = idx % WW;
            score = __uint_as_float((unsigned)(w >> 32));
            cls = 0.0f; vf = 1.0f;

            const int WP = WW + 1;
            const int g0 = (hh * WP + ww) * 3;
            const int g1 = ((hh + 1) * WP + (ww + 1)) * 3;
            const float cx = 0.5f * (grid[g0 + 0] + grid[g1 + 0]);
            const float cy = 0.5f * (grid[g0 + 1] + grid[g1 + 1]);
            const float cz = 0.5f * (grid[g0 + 2] + grid[g1 + 2]);

            const int o = hh * WW + ww;
            px = pos_off[0 * HH * WW + o] * 0.5f  + cx;
            py = pos_off[1 * HH * WW + o] * 0.36f + cy;
            pz = pos_off[2 * HH * WW + o] * 0.5f  + cz;
            dx = expf(dim_off[0 * HH * WW + o] * 0.085f + 0.42f);
            dy = expf(dim_off[1 * HH * WW + o] * 0.067f + 0.48f);
            dz = expf(dim_off[2 * HH * WW + o] * 0.115f + 1.35f);
            ang = atan2f(ang_off[1 * HH * WW + o], ang_off[0 * HH * WW + o]);
        }
        out[tid]           = score;
        out[50 + tid]      = cls;
        out[100 + 3 * tid] = px;
        out[101 + 3 * tid] = py;
        out[102 + 3 * tid] = pz;
        out[250 + 3 * tid] = dx;
        out[251 + 3 * tid] = dy;
        out[252 + 3 * tid] = dz;
        out[400 + tid]     = ang;
        out[450 + tid]     = vf;
    }
}

extern "C" void kernel_launch(void* const* d_in, const int* in_sizes, int n_in,
                              void* d_out, int out_size)
{
    const float* heat = (const float*)d_in[0];
    const float* pos  = (const float*)d_in[1];
    const float* dim  = (const float*)d_in[2];
    const float* ang  = (const float*)d_in[3];
    const float* grid = (const float*)d_in[4];
    const float* kk   = (const float*)d_in[5];
    float* out = (float*)d_out;

    // >48KB dynamic smem needs opt-in (host attribute; idempotent; no alloc;
    // safe under graph capture).
    cudaFuncSetAttribute(final_kernel, cudaFuncAttributeMaxDynamicSharedMemorySize,
                         NG * (int)sizeof(unsigned long long));

    peaks_kernel<<<NBLK2, 1024>>>(heat, kk);
    final_kernel<<<1, 1024, NG * sizeof(unsigned long long)>>>(pos, dim, ang, grid, out);
}

// round 13
// speedup vs baseline: 2.4749x; 1.0082x over previous
#include <cuda_runtime.h>
#include <math.h>

// Fixed problem: C=1, H=W=2048
#define HH 2048
#define WW 2048
#define NMS_T 0.05f
#define KTOP 50

// 2px/lane, 56-col x 16-row strips: 37 x 128 = 4736 strips = 148 blocks x 32 warps.
#define OUTW 56
#define SX2 37
#define SY2 128
#define STRIPH2 16
#define WPB2 32
#define NBLK2 148
#define SLOTS 64            // per-block output slice (superset of block top-50)
#define NG (NBLK2*SLOTS)    // 9472 keys

#define WCAP 144            // per-warp segment (expected ~46 peaks, 3x margin)
#define NSEG (WPB2*WCAP)    // 4608 slots = 36KB
#define NBINS 2048
#define BINBASE 31385       // float_bits(0.05f) >> 15
#define BND 192
#define RING 6              // float2 prefetch ring
#define PITER2 24           // 4*RING >= STRIPH2+6 rows

__device__ unsigned long long g_cand[NG];
__device__ int g_done = 0;  // finisher ticket; reset to 0 by finisher each run

__device__ __forceinline__ int keybin(unsigned long long k) {
    int b = (int)(k >> 47) - BINBASE;
    return b < 0 ? 0 : (b > NBINS - 1 ? NBINS - 1 : b);
}
__device__ __forceinline__ int keybin2(unsigned long long k) {
    return (int)((unsigned)(k >> 36) & 0x7FFu);
}

// Warp 0: scan histogram top-down from startbin; find B with cum(>B) < target
// <= cum(>=B). cA = cum(>B). B=-1 if total<target. Empty chunks ballot-skipped.
__device__ __forceinline__ void find_thresh(const int* hist, int lane, int target,
                                            int startbin, int* s_B, int* s_cA) {
    int cum = 0, B = -1, cA = 0;
    int base0 = startbin & ~31;
    if (base0 > NBINS - 32) base0 = NBINS - 32;
    for (int base = base0; base >= 0; base -= 32) {
        int h = hist[base + 31 - lane];
        if (__ballot_sync(0xffffffffu, h != 0) == 0u) continue;
        int pfx = h;
#pragma unroll
        for (int off = 1; off < 32; off <<= 1) {
            int o = __shfl_up_sync(0xffffffffu, pfx, off);
            if (lane >= off) pfx += o;
        }
        int tot = __shfl_sync(0xffffffffu, pfx, 31);
        if (cum + tot >= target) {
            unsigned bal = __ballot_sync(0xffffffffu, cum + pfx >= target);
            const int sel = __ffs(bal) - 1;
            B = base + 31 - sel;
            cA = cum + __shfl_sync(0xffffffffu, pfx, sel)
                     - __shfl_sync(0xffffffffu, h, sel);
            break;
        }
        cum += tot;
    }
    if (B < 0) cA = cum;
    if (lane == 0) { *s_B = B; *s_cA = cA; }
}

// Warp 0: exact top-`need` of boundary keys (small sets only).
__device__ __forceinline__ void bnd_select(unsigned long long* bnd, int nb, int need,
                                           unsigned long long* out, int lane) {
    for (int r = 0; r < need; r++) {
        unsigned long long lm = 0ull; int li = 0;
        for (int i = lane; i < nb; i += 32) {
            unsigned long long k = bnd[i];
            if (k > lm) { lm = k; li = i; }
        }
#pragma unroll
        for (int off = 16; off; off >>= 1) {
            unsigned long long ok = __shfl_down_sync(0xffffffffu, lm, off);
            int oi = __shfl_down_sync(0xffffffffu, li, off);
            if (ok > lm) { lm = ok; li = oi; }
        }
        if (lane == 0) { out[r] = lm; bnd[li] = 0ull; }
        __syncwarp();
    }
}

// ---------------------------------------------------------------------------
// 2px/lane strip pipeline (16-row strips), register-cursor appends (no atomics).
// ---------------------------------------------------------------------------
template<bool EDGE>
__device__ __forceinline__ void strip_loop2(
    const float* __restrict__ heat, int r0, int c0, bool lane_in, bool out_lane,
    int lane,
    float rw0, float rw1, float rw2, float rw3, float rw4,
    float cw0, float cw1, float cw3, float cw4,
    unsigned long long* s_seg)
{
    const float NEG = -3.402823466e38f;
    const int rmax_eff = min(r0 + STRIPH2 + 2, HH - 1);
    const unsigned FULL = 0xffffffffu;

    float2 vb[RING];
#pragma unroll
    for (int j = 0; j < RING; j++) {
        const int r = r0 - 3 + j;
        float2 nv = make_float2(0.f, 0.f);
        if (lane_in && r >= 0 && r <= rmax_eff)
            nv = *reinterpret_cast<const float2*>(heat + r * WW + c0);
        vb[j] = nv;
    }

    float2 h0 = {0,0}, h1 = {0,0}, h2 = {0,0}, h3 = {0,0}, h4 = {0,0};
    float2 sA = {0,0}, sB = {0,0}, sC = {0,0};
    float2 p0 = {0,0}, p1 = {0,0}, p2 = {0,0};
    const int c1 = c0 + 1;
    int wcnt = 0;

    for (int rb = 0; rb < PITER2; rb += RING) {
#pragma unroll
        for (int u = 0; u < RING; u++) {
            const int ri = rb + u;
            const float2 v = vb[u];
            {   // prefetch (pr >= r0+3 > 0)
                const int pr = r0 - 3 + ri + RING;
                float2 nv = make_float2(0.f, 0.f);
                if (lane_in && pr <= rmax_eff)
                    nv = *reinterpret_cast<const float2*>(heat + pr * WW + c0);
                vb[u] = nv;
            }
            const float pmx = __shfl_sync(FULL, v.x, lane - 1);
            const float pmy = __shfl_sync(FULL, v.y, lane - 1);
            const float npx = __shfl_sync(FULL, v.x, lane + 1);
            const float npy = __shfl_sync(FULL, v.y, lane + 1);
            const float hsx = rw0*pmx + rw1*pmy + rw2*v.x + rw3*v.y + rw4*npx;
            const float hsy = rw0*pmy + rw1*v.x + rw2*v.y + rw3*npx + rw4*npy;
            h0 = h1; h1 = h2; h2 = h3; h3 = h4; h4 = make_float2(hsx, hsy);
            const float smx = cw0*h0.x + cw1*h1.x + h2.x + cw3*h3.x + cw4*h4.x;
            const float smy = cw0*h0.y + cw1*h1.y + h2.y + cw3*h3.y + cw4*h4.y;
            sA = sB; sB = sC; sC = make_float2(smx, smy);
            float vmx, vmy;
            if (EDGE) {
                const int m = r0 - 5 + ri;
                const bool gA = (m - 2) >= 0;
                const bool gB = (unsigned)(m - 1) < (unsigned)HH;
                const bool gC = (unsigned)m < (unsigned)HH;
                vmx = fmaxf(gA ? sA.x : NEG, fmaxf(gB ? sB.x : NEG, gC ? sC.x : NEG));
                vmy = fmaxf(gA ? sA.y : NEG, fmaxf(gB ? sB.y : NEG, gC ? sC.y : NEG));
            } else {
                vmx = fmaxf(sA.x, fmaxf(sB.x, sC.x));
                vmy = fmaxf(sA.y, fmaxf(sB.y, sC.y));
            }
            const float prev_vm1 = __shfl_sync(FULL, vmy, lane - 1);
            const float next_vm0 = __shfl_sync(FULL, vmx, lane + 1);
            const float2 raw = p0;
            p0 = p1; p1 = p2; p2 = v;

            bool pk0 = false, pk1 = false;
            unsigned long long k0 = 0ull, k1 = 0ull;
            if ((unsigned)(ri - 6) < (unsigned)STRIPH2 && out_lane) {
                float w0 = fmaxf(vmx, vmy);
                if (c0 > 0) w0 = fmaxf(w0, prev_vm1);
                float w1 = fmaxf(vmx, vmy);
                if (c1 < WW - 1) w1 = fmaxf(w1, next_vm0);
                const int t = r0 + ri - 6;
                if (sB.x >= w0 && raw.x > NMS_T) {
                    pk0 = true;
                    const unsigned idx = (unsigned)(t * WW + c0);
                    k0 = ((unsigned long long)__float_as_uint(raw.x) << 32)
                         | (0xFFFFFFFFu - idx);
                }
                if (sB.y >= w1 && raw.y > NMS_T) {
                    pk1 = true;
                    const unsigned idx = (unsigned)(t * WW + c1);
                    k1 = ((unsigned long long)__float_as_uint(raw.y) << 32)
                         | (0xFFFFFFFFu - idx);
                }
            }
            const unsigned m0 = __ballot_sync(FULL, pk0);
            const unsigned m1 = __ballot_sync(FULL, pk1);
            if (m0 | m1) {
                const unsigned lt = (1u << lane) - 1u;
                if (pk0) {
                    const int p = wcnt + __popc(m0 & lt);
                    if (p < WCAP) s_seg[p] = k0;
                }
                if (pk1) {
                    const int p = wcnt + __popc(m0) + __popc(m1 & lt);
                    if (p < WCAP) s_seg[p] = k1;
                }
                wcnt += __popc(m0) + __popc(m1);
            }
        }
    }
}

// ---------------------------------------------------------------------------
// Single fused kernel: strips -> block top-50 superset -> g_cand slice ->
// last block (ticket pattern) runs global selection + epilogue on L2-hot data.
// Output (f32, 500): scores[50]|classids[50]|pos[50,3]|dim[50,3]|angles[50]|valid[50]
// ---------------------------------------------------------------------------
__global__ void __launch_bounds__(1024) fused_kernel(
    const float* __restrict__ heat, const float* __restrict__ kk,
    const float* __restrict__ pos_off, const float* __restrict__ dim_off,
    const float* __restrict__ ang_off, const float* __restrict__ grid,
    float* __restrict__ out)
{
    __shared__ unsigned long long s_buf[NSEG];      // 36KB
    __shared__ int s_hist[NBINS];                   // 8KB
    __shared__ unsigned long long s_bnd[BND];
    __shared__ unsigned long long s_out[SLOTS];
    __shared__ unsigned long long s_win[KTOP];
    __shared__ unsigned long long s_sorted[KTOP];
    __shared__ unsigned long long s_maxk;
    __shared__ int s_ctrD, s_ctrB, s_B, s_cA, s_nt, s_ticket;

    const int tid = threadIdx.x, lane = tid & 31, wid = tid >> 5;
    for (int i = tid; i < NSEG; i += 1024) s_buf[i] = 0ull;
    for (int i = tid; i < NBINS; i += 1024) s_hist[i] = 0;
    if (tid < SLOTS) s_out[tid] = 0ull;
    if (tid == 0) { s_maxk = 0ull; s_ctrD = 0; s_ctrB = 0; }
    __syncthreads();

    // ---- phase 1: strip conv + peak detect ----
    const int s = blockIdx.x * WPB2 + wid;          // 0..4735
    const int sx = s % SX2, sy = s / SX2;
    const int c0 = sx * OUTW - 4 + 2 * lane;        // even
    const bool lane_in = (c0 >= 0) && (c0 < WW);
    const int r0 = sy * STRIPH2;
    const bool out_lane = (lane >= 2) && (lane <= 29);

    const float rw0 = kk[10], rw1 = kk[11], rw2 = kk[12], rw3 = kk[13], rw4 = kk[14];
    const float inv = 1.0f / kk[12];
    const float cw0 = kk[2] * inv, cw1 = kk[7] * inv, cw3 = kk[17] * inv, cw4 = kk[22] * inv;

    unsigned long long* seg = s_buf + wid * WCAP;
    const bool edge = (sy == 0) || (sy == SY2 - 1);
    if (edge)
        strip_loop2<true >(heat, r0, c0, lane_in, out_lane, lane,
                           rw0, rw1, rw2, rw3, rw4, cw0, cw1, cw3, cw4, seg);
    else
        strip_loop2<false>(heat, r0, c0, lane_in, out_lane, lane,
                           rw0, rw1, rw2, rw3, rw4, cw0, cw1, cw3, cw4, seg);

    __syncthreads();
    // ---- phase 2: block-local top-50 superset ----
    unsigned long long lmax = 0ull;
    for (int i = tid; i < NSEG; i += 1024) {
        const unsigned long long k = s_buf[i];
        if (k) {
            atomicAdd(&s_hist[keybin(k)], 1);
            if (k > lmax) lmax = k;
        }
    }
#pragma unroll
    for (int off = 16; off; off >>= 1) {
        unsigned long long o = __shfl_down_sync(0xffffffffu, lmax, off);
        lmax = (o > lmax) ? o : lmax;
    }
    if (lane == 0 && lmax) atomicMax(&s_maxk, lmax);
    __syncthreads();
    if (wid == 0) find_thresh(s_hist, lane, KTOP, keybin(s_maxk), &s_B, &s_cA);
    __syncthreads();
    {
        const int B = s_B;
        for (int i = tid; i < NSEG; i += 1024) {
            const unsigned long long k = s_buf[i];
            if (!k) continue;
            const int b = keybin(k);
            if (B < 0 || b > B) {
                const int p = atomicAdd(&s_ctrD, 1);
                if (p < SLOTS) s_out[p] = k;
            } else if (b == B) {
                const int p = atomicAdd(&s_ctrB, 1);
                if (p < BND) s_bnd[p] = k;
            }
        }
        __syncthreads();
        const int c = s_ctrD;
        const int nb = min(s_ctrB, BND);
        if (B >= 0) {
            if (c + nb <= SLOTS) {
                if (tid < nb) s_out[c + tid] = s_bnd[tid];
            } else if (wid == 0) {
                bnd_select(s_bnd, nb, KTOP - c, s_out + c, lane);
            }
        }
        __syncthreads();
        if (tid < SLOTS) g_cand[blockIdx.x * SLOTS + tid] = s_out[tid];
    }

    // ---- phase 3: last-block-done ticket ----
    __threadfence();                                // publish g_cand slice
    if (tid == 0) s_ticket = atomicAdd(&g_done, 1);
    __syncthreads();
    if (s_ticket != NBLK2 - 1) return;

    // ---- finisher: global top-50 over NG L2-hot keys ----
    for (int i = tid; i < NBINS; i += 1024) s_hist[i] = 0;
    if (tid == 0) { s_maxk = 0ull; s_ctrD = 0; s_ctrB = 0; }
    __syncthreads();

    unsigned long long gmax = 0ull;
    for (int i = tid; i < NG; i += 1024) {
        const unsigned long long k = g_cand[i];
        if (k) {
            atomicAdd(&s_hist[keybin(k)], 1);
            if (k > gmax) gmax = k;
        }
    }
#pragma unroll
    for (int off = 16; off; off >>= 1) {
        unsigned long long o = __shfl_down_sync(0xffffffffu, gmax, off);
        gmax = (o > gmax) ? o : gmax;
    }
    if (lane == 0 && gmax) atomicMax(&s_maxk, gmax);
    __syncthreads();
    if (wid == 0) find_thresh(s_hist, lane, KTOP, keybin(s_maxk), &s_B, &s_cA);
    __syncthreads();
    const int B1 = s_B, cA1 = s_cA;

    int B2 = -1;
    if (B1 >= 0) {
        // level 2: re-bin bin-B1 keys by next 11 float bits (16-ulp sub-bins)
        for (int i = tid; i < NBINS; i += 1024) s_hist[i] = 0;
        if (tid == 0) s_maxk = 0ull;
        __syncthreads();
        unsigned long long gmax2 = 0ull;
        for (int i = tid; i < NG; i += 1024) {
            const unsigned long long k = g_cand[i];
            if (k && keybin(k) == B1) {
                atomicAdd(&s_hist[keybin2(k)], 1);
                if (k > gmax2) gmax2 = k;
            }
        }
#pragma unroll
        for (int off = 16; off; off >>= 1) {
            unsigned long long o = __shfl_down_sync(0xffffffffu, gmax2, off);
            gmax2 = (o > gmax2) ? o : gmax2;
        }
        if (lane == 0 && gmax2) atomicMax(&s_maxk, gmax2);
        __syncthreads();
        if (wid == 0) find_thresh(s_hist, lane, KTOP - cA1, keybin2(s_maxk),
                                  &s_B, &s_cA);
        __syncthreads();
        B2 = s_B;                                   // always >= 0 here
    }

    // classify: definite vs boundary
    for (int i = tid; i < NG; i += 1024) {
        const unsigned long long k = g_cand[i];
        if (!k) continue;
        const int b1 = keybin(k);
        bool def = false, bnd = false;
        if (B1 < 0 || b1 > B1) def = true;
        else if (b1 == B1) {
            const int b2 = keybin2(k);
            if (b2 > B2) def = true;
            else if (b2 == B2) bnd = true;
        }
        if (def) {
            const int p = atomicAdd(&s_ctrD, 1);
            if (p < KTOP) s_win[p] = k;             // cA1+cA2 < KTOP guaranteed
        } else if (bnd) {
            const int p = atomicAdd(&s_ctrB, 1);
            if (p < BND) s_bnd[p] = k;
        }
    }
    __syncthreads();
    {
        const int c = s_ctrD;
        const int nb = min(s_ctrB, BND);
        if (B1 < 0) {
            if (tid == 0) s_nt = min(c, KTOP);
        } else {
            const int need = KTOP - c;              // nb >= need by construction
            if (nb <= need) {
                if (tid < nb) s_win[c + tid] = s_bnd[tid];
                if (tid == 0) s_nt = c + nb;
            } else {
                if (wid == 0) bnd_select(s_bnd, nb, need, s_win + c, lane);
                if (tid == 0) s_nt = KTOP;
            }
        }
    }
    __syncthreads();
    const int nt = s_nt;
    if (tid < nt) {                                 // rank sort (keys unique)
        const unsigned long long k = s_win[tid];
        int rank = 0;
        for (int j = 0; j < nt; j++) rank += (s_win[j] > k);
        s_sorted[rank] = k;
    }
    __syncthreads();

    if (tid < KTOP) {
        const bool valid = tid < nt;
        float score = 0.f, cls = -1.f, px = 0.f, py = 0.f, pz = 0.f;
        float dx = 0.f, dy = 0.f, dz = 0.f, ang = 0.f, vf = 0.f;
        if (valid) {
            const unsigned long long w = s_sorted[tid];
            const unsigned idx = 0xFFFFFFFFu - (unsigned)(w & 0xFFFFFFFFull);
            const int hh = idx / WW, ww = idx % WW;
            score = __uint_as_float((unsigned)(w >> 32));
            cls = 0.0f; vf = 1.0f;

            const int WP = WW + 1;
            const int g0 = (hh * WP + ww) * 3;
            const int g1 = ((hh + 1) * WP + (ww + 1)) * 3;
            const float cx = 0.5f * (grid[g0 + 0] + grid[g1 + 0]);
            const float cy = 0.5f * (grid[g0 + 1] + grid[g1 + 1]);
            const float cz = 0.5f * (grid[g0 + 2] + grid[g1 + 2]);

            const int o = hh * WW + ww;
            px = pos_off[0 * HH * WW + o] * 0.5f  + cx;
            py = pos_off[1 * HH * WW + o] * 0.36f + cy;
            pz = pos_off[2 * HH * WW + o] * 0.5f  + cz;
            dx = expf(dim_off[0 * HH * WW + o] * 0.085f + 0.42f);
            dy = expf(dim_off[1 * HH * WW + o] * 0.067f + 0.48f);
            dz = expf(dim_off[2 * HH * WW + o] * 0.115f + 1.35f);
            ang = atan2f(ang_off[1 * HH * WW + o], ang_off[0 * HH * WW + o]);
        }
        out[tid]           = score;
        out[50 + tid]      = cls;
        out[100 + 3 * tid] = px;
        out[101 + 3 * tid] = py;
        out[102 + 3 * tid] = pz;
        out[250 + 3 * tid] = dx;
        out[251 + 3 * tid] = dy;
        out[252 + 3 * tid] = dz;
        out[400 + tid]     = ang;
        out[450 + tid]     = vf;
    }
    __syncthreads();
    if (tid == 0) g_done = 0;                       // reset for next graph replay
}

extern "C" void kernel_launch(void* const* d_in, const int* in_sizes, int n_in,
                              void* d_out, int out_size)
{
    const float* heat = (const float*)d_in[0];
    const float* pos  = (const float*)d_in[1];
    const float* dim  = (const float*)d_in[2];
    const float* ang  = (const float*)d_in[3];
    const float* grid = (const float*)d_in[4];
    const float* kk   = (const float*)d_in[5];
    float* out = (float*)d_out;

    fused_kernel<<<NBLK2, 1024>>>(heat, kk, pos, dim, ang, grid, out);
}